// round 3
// baseline (speedup 1.0000x reference)
#include <cuda_runtime.h>
#include <cstdint>

#define DG 128
#define MAXN 100000

// Scratch (device globals — no allocation allowed).
// __align__(16): all of these are accessed via float4 loads/stores/atomics.
__device__ __align__(16) float g_agg0[MAXN * 4];  // x,y,z = sum x[src]; w = degree
__device__ __align__(16) float g_h[MAXN * DG];    // h after layer0 + LN
__device__ __align__(16) float g_agg[MAXN * DG];  // layer1 agg buffer

// ---------------------------------------------------------------------------
// Kernel 1: zero the scratch buffers (must happen every launch - graph replay)
// ---------------------------------------------------------------------------
__global__ void zero_kernel(int n) {
    int i = blockIdx.x * blockDim.x + threadIdx.x;
    float4 z = make_float4(0.f, 0.f, 0.f, 0.f);
    if (i < n) {
        ((float4*)g_agg0)[i] = z;              // n float4s = n*4 floats
    } else if (i < n + n * 32) {
        ((float4*)g_agg)[i - n] = z;           // n*32 float4s = n*128 floats
    }
}

// ---------------------------------------------------------------------------
// Kernel 2: edge pass 0 — scatter x[src] (3 dims) + degree count, one float4
// RED per edge. w-component accumulates 1.0 per edge = degree.
// edge_index arrives as int32 (harness converts int64 inputs to int32).
// ---------------------------------------------------------------------------
__global__ void edge0_kernel(const float* __restrict__ x,
                             const int* __restrict__ ei, int nE) {
    int e = blockIdx.x * blockDim.x + threadIdx.x;
    if (e >= nE) return;
    int s = ei[e];
    int d = ei[nE + e];
    float4 v = make_float4(x[3 * s], x[3 * s + 1], x[3 * s + 2], 1.0f);
    atomicAdd((float4*)(g_agg0 + 4 * (size_t)d), v);
}

// ---------------------------------------------------------------------------
// Kernel 3: layer0 linear + relu + layernorm. One block of 128 threads
// processes NPB0 nodes sequentially; weights live in smem.
// ---------------------------------------------------------------------------
__device__ __forceinline__ float warp_sum(float v) {
#pragma unroll
    for (int o = 16; o; o >>= 1) v += __shfl_xor_sync(0xffffffffu, v, o);
    return v;
}

#define NPB0 64
__global__ __launch_bounds__(128) void layer0_kernel(
    const float* __restrict__ x, const float* __restrict__ Wl,
    const float* __restrict__ Wr, const float* __restrict__ b,
    const float* __restrict__ g, const float* __restrict__ be, int n) {
    __shared__ float swl[3][DG], swr[3][DG], sb[DG], sg[DG], sbe[DG];
    __shared__ float red1[4], red2[4];
    int j = threadIdx.x;
#pragma unroll
    for (int k = 0; k < 3; k++) {
        swl[k][j] = Wl[k * DG + j];
        swr[k][j] = Wr[k * DG + j];
    }
    sb[j] = b[j]; sg[j] = g[j]; sbe[j] = be[j];
    __syncthreads();

    int base = blockIdx.x * NPB0;
    int wid = j >> 5, lane = j & 31;
    for (int i = 0; i < NPB0; i++) {
        int node = base + i;
        if (node >= n) break;   // uniform across block (nodes ascend)
        float4 a = *((const float4*)g_agg0 + node);
        float inv = 1.f / fmaxf(a.w, 1.f);
        float a0 = a.x * inv, a1 = a.y * inv, a2 = a.z * inv;
        float x0 = x[3 * node], x1 = x[3 * node + 1], x2 = x[3 * node + 2];
        float v = sb[j]
                + a0 * swl[0][j] + a1 * swl[1][j] + a2 * swl[2][j]
                + x0 * swr[0][j] + x1 * swr[1][j] + x2 * swr[2][j];
        v = fmaxf(v, 0.f);
        // layernorm over 128 dims
        float s = warp_sum(v);
        if (lane == 0) red1[wid] = s;
        __syncthreads();
        float mu = (red1[0] + red1[1] + red1[2] + red1[3]) * (1.f / DG);
        float d = v - mu;
        float s2 = warp_sum(d * d);
        if (lane == 0) red2[wid] = s2;
        __syncthreads();
        float var = (red2[0] + red2[1] + red2[2] + red2[3]) * (1.f / DG);
        g_h[(size_t)node * DG + j] = d * rsqrtf(var + 1e-5f) * sg[j] + sbe[j];
        __syncthreads();
    }
}

// ---------------------------------------------------------------------------
// Kernel 4: edge pass 1 — scatter h[src] (128 dims) onto agg[dst].
// One warp per edge; each lane handles one float4 chunk (32 chunks * 4 = 128).
// ---------------------------------------------------------------------------
__global__ void edge1_kernel(const int* __restrict__ ei, int nE) {
    long long gid = (long long)blockIdx.x * blockDim.x + threadIdx.x;
    int e = (int)(gid >> 5);
    if (e >= nE) return;
    int c = (int)(gid & 31);
    int s = ei[e];
    int d = ei[nE + e];
    float4 v = *(const float4*)(g_h + (size_t)s * DG + c * 4);
    atomicAdd((float4*)(g_agg + (size_t)d * DG + c * 4), v);
}

// ---------------------------------------------------------------------------
// Kernel 5: layer1 output GEMM + relu.
// Block tile: 64 nodes x 128 cols, 128 threads, each thread 8 rows x 8 cols.
// out[n,j] = relu( (agg[n]*inv_deg) @ Wl1 + h[n] @ Wr1 + b1 )
// ---------------------------------------------------------------------------
#define KC 16
__global__ __launch_bounds__(128) void out_kernel(
    const float* __restrict__ Wl, const float* __restrict__ Wr,
    const float* __restrict__ b1, float* __restrict__ out, int n) {
    __shared__ __align__(16) float sWl[KC][DG], sWr[KC][DG];
    __shared__ __align__(16) float sA[64][KC + 1], sH[64][KC + 1];

    int tid = threadIdx.x;
    int n0 = blockIdx.x * 64;
    int rg = tid >> 4;           // 0..7 -> rows rg*8 .. rg*8+7
    int cg = tid & 15;           // 0..15 -> cols cg*4..+3 and 64+cg*4..+3
    int r0 = rg * 8;

    float4 acc0[8], acc1[8];
#pragma unroll
    for (int i = 0; i < 8; i++) {
        acc0[i] = make_float4(0.f, 0.f, 0.f, 0.f);
        acc1[i] = make_float4(0.f, 0.f, 0.f, 0.f);
    }

    // loader mapping: thread -> (node, k-half)
    int lnode = tid >> 1;        // 0..63
    int lhalf = tid & 1;         // 0..1 -> k offset 8*lhalf
    bool lact = (n0 + lnode) < n;
    float invl = lact ? 1.f / fmaxf(g_agg0[(size_t)(n0 + lnode) * 4 + 3], 1.f) : 0.f;

    for (int kc = 0; kc < DG; kc += KC) {
        __syncthreads();
        // load W tiles: KC x 128 each = 512 float4 per matrix, 4 per thread
#pragma unroll
        for (int q = 0; q < 4; q++) {
            int idx = tid + q * 128;       // float4 index 0..511
            int kr = idx >> 5;             // 0..15
            int cc = (idx & 31) * 4;
            *(float4*)&sWl[kr][cc] = *(const float4*)&Wl[(size_t)(kc + kr) * DG + cc];
            *(float4*)&sWr[kr][cc] = *(const float4*)&Wr[(size_t)(kc + kr) * DG + cc];
        }
        // load A/H tiles: 64 nodes x KC, apply inv_deg to A at load
#pragma unroll
        for (int q = 0; q < 2; q++) {
            int kk = lhalf * 8 + q * 4;
            float4 av = make_float4(0.f, 0.f, 0.f, 0.f);
            float4 hv = make_float4(0.f, 0.f, 0.f, 0.f);
            if (lact) {
                av = *(const float4*)&g_agg[(size_t)(n0 + lnode) * DG + kc + kk];
                hv = *(const float4*)&g_h[(size_t)(n0 + lnode) * DG + kc + kk];
                av.x *= invl; av.y *= invl; av.z *= invl; av.w *= invl;
            }
            sA[lnode][kk + 0] = av.x; sA[lnode][kk + 1] = av.y;
            sA[lnode][kk + 2] = av.z; sA[lnode][kk + 3] = av.w;
            sH[lnode][kk + 0] = hv.x; sH[lnode][kk + 1] = hv.y;
            sH[lnode][kk + 2] = hv.z; sH[lnode][kk + 3] = hv.w;
        }
        __syncthreads();

#pragma unroll
        for (int k = 0; k < KC; k++) {
            float4 wl0 = *(float4*)&sWl[k][cg * 4];
            float4 wl1 = *(float4*)&sWl[k][64 + cg * 4];
            float4 wr0 = *(float4*)&sWr[k][cg * 4];
            float4 wr1 = *(float4*)&sWr[k][64 + cg * 4];
#pragma unroll
            for (int i = 0; i < 8; i++) {
                float a = sA[r0 + i][k];
                float h = sH[r0 + i][k];
                acc0[i].x += a * wl0.x + h * wr0.x;
                acc0[i].y += a * wl0.y + h * wr0.y;
                acc0[i].z += a * wl0.z + h * wr0.z;
                acc0[i].w += a * wl0.w + h * wr0.w;
                acc1[i].x += a * wl1.x + h * wr1.x;
                acc1[i].y += a * wl1.y + h * wr1.y;
                acc1[i].z += a * wl1.z + h * wr1.z;
                acc1[i].w += a * wl1.w + h * wr1.w;
            }
        }
    }

    float4 bv0 = *(const float4*)&b1[cg * 4];
    float4 bv1 = *(const float4*)&b1[64 + cg * 4];
#pragma unroll
    for (int i = 0; i < 8; i++) {
        int node = n0 + r0 + i;
        if (node < n) {
            float4 o;
            o.x = fmaxf(acc0[i].x + bv0.x, 0.f);
            o.y = fmaxf(acc0[i].y + bv0.y, 0.f);
            o.z = fmaxf(acc0[i].z + bv0.z, 0.f);
            o.w = fmaxf(acc0[i].w + bv0.w, 0.f);
            *(float4*)&out[(size_t)node * DG + cg * 4] = o;
            o.x = fmaxf(acc1[i].x + bv1.x, 0.f);
            o.y = fmaxf(acc1[i].y + bv1.y, 0.f);
            o.z = fmaxf(acc1[i].z + bv1.z, 0.f);
            o.w = fmaxf(acc1[i].w + bv1.w, 0.f);
            *(float4*)&out[(size_t)node * DG + 64 + cg * 4] = o;
        }
    }
}

// ---------------------------------------------------------------------------
extern "C" void kernel_launch(void* const* d_in, const int* in_sizes, int n_in,
                              void* d_out, int out_size) {
    const float* x   = (const float*)d_in[0];
    const int*   ei  = (const int*)d_in[1];     // int64 in reference -> int32 on device
    const float* Wl0 = (const float*)d_in[2];
    const float* Wr0 = (const float*)d_in[3];
    const float* b0  = (const float*)d_in[4];
    const float* Wl1 = (const float*)d_in[5];
    const float* Wr1 = (const float*)d_in[6];
    const float* b1  = (const float*)d_in[7];
    const float* g   = (const float*)d_in[8];
    const float* be  = (const float*)d_in[9];
    float* out = (float*)d_out;

    int n  = in_sizes[0] / 3;
    int nE = in_sizes[1] / 2;

    int z4 = n * 33;  // n float4 (agg0) + n*32 float4 (agg)
    zero_kernel<<<(z4 + 255) / 256, 256>>>(n);
    edge0_kernel<<<(nE + 255) / 256, 256>>>(x, ei, nE);
    layer0_kernel<<<(n + NPB0 - 1) / NPB0, 128>>>(x, Wl0, Wr0, b0, g, be, n);
    long long w = (long long)nE * 32;
    edge1_kernel<<<(int)((w + 255) / 256), 256>>>(ei, nE);
    out_kernel<<<(n + 63) / 64, 128>>>(Wl1, Wr1, b1, out, n);
}